// round 1
// baseline (speedup 1.0000x reference)
#include <cuda_runtime.h>
#include <math.h>
#include <stdint.h>

// Problem constants (fixed by the dataset)
#define NN 50000
#define FF 128
#define HH 128

// Scratch: segment-sum accumulators (allocation-free rule -> __device__ globals)
__device__ float g_num[NN * HH];   // sum of messages per destination node
__device__ float g_deg[NN];        // edge count per destination node

// ---------------------------------------------------------------------------
// Zero the accumulators (d_out is poisoned; scratch must be zeroed each call)
// ---------------------------------------------------------------------------
__global__ void zero_kernel(int n_num, int n_deg)
{
    int total = n_num + n_deg;
    for (int i = blockIdx.x * blockDim.x + threadIdx.x; i < total;
         i += gridDim.x * blockDim.x) {
        if (i < n_num) g_num[i] = 0.0f;
        else           g_deg[i - n_num] = 0.0f;
    }
}

__device__ __forceinline__ float silu_f(float x)
{
    // x * sigmoid(x) = x / (1 + e^-x); __expf/__fdividef rel err ~1e-6 << 1e-3 gate
    return __fdividef(x, 1.0f + __expf(-x));
}

// ---------------------------------------------------------------------------
// Edge kernel: per edge e
//   dist = arccosh(1 + |x_r - x_c|^2 / (2 z_r z_c))
//   m = silu(silu([h_r, h_c, dist] @ We1 + be1) @ We2 + be2)
//   g_num[row] += m ; g_deg[row] += 1
// Whole We1 (257x128) + We2 (128x128) resident in SMEM; warp-per-edge GEMV.
// ---------------------------------------------------------------------------
__global__ __launch_bounds__(512, 1)
void edge_kernel(const float* __restrict__ xz,
                 const float* __restrict__ h,
                 const float* __restrict__ We1,
                 const float* __restrict__ be1,
                 const float* __restrict__ We2,
                 const float* __restrict__ be2,
                 const int*   __restrict__ row,
                 const int*   __restrict__ col,
                 int E)
{
    extern __shared__ float sm[];
    float* W1 = sm;                       // 257*128
    float* W2 = W1 + 257 * 128;           // 128*128
    float* b1 = W2 + 128 * 128;           // 128
    float* b2 = b1 + 128;                 // 128

    for (int i = threadIdx.x; i < 257 * 128; i += blockDim.x) W1[i] = We1[i];
    for (int i = threadIdx.x; i < 128 * 128; i += blockDim.x) W2[i] = We2[i];
    if (threadIdx.x < 128)      b1[threadIdx.x] = be1[threadIdx.x];
    else if (threadIdx.x < 256) b2[threadIdx.x - 128] = be2[threadIdx.x - 128];
    __syncthreads();

    const int lane = threadIdx.x & 31;
    const int warp = threadIdx.x >> 5;
    const int nwarp = blockDim.x >> 5;
    const int j4 = lane << 2;             // this lane owns outputs j4..j4+3

    const float4 bb1 = *reinterpret_cast<const float4*>(&b1[j4]);
    const float4 bb2 = *reinterpret_cast<const float4*>(&b2[j4]);

    for (int e = blockIdx.x * nwarp + warp; e < E; e += gridDim.x * nwarp) {
        const int r = row[e];
        const int c = col[e];

        // AdS distance (all lanes compute redundantly; loads broadcast from L1)
        const float dx = xz[3 * r + 0] - xz[3 * c + 0];
        const float dy = xz[3 * r + 1] - xz[3 * c + 1];
        const float zr = xz[3 * r + 2];
        const float zc = xz[3 * c + 2];
        const float dz = zr - zc;
        const float u  = (dx * dx + dy * dy + dz * dz) / (2.0f * zr * zc);
        const float dist = acoshf(1.0f + u);

        // Gather h[r], h[c]: lane holds elements {i*32+lane}
        float hr[4], hc[4];
        #pragma unroll
        for (int i = 0; i < 4; i++) {
            hr[i] = h[r * 128 + i * 32 + lane];
            hc[i] = h[c * 128 + i * 32 + lane];
        }

        // ---- layer 1: [h_r | h_c | dist] @ We1 + be1 ----
        float a0 = bb1.x, a1 = bb1.y, a2 = bb1.z, a3 = bb1.w;
        #pragma unroll
        for (int i = 0; i < 4; i++) {
            const float xr = hr[i];
            #pragma unroll
            for (int s = 0; s < 32; s++) {
                const float xa = __shfl_sync(0xffffffffu, xr, s);
                const float4 w = *reinterpret_cast<const float4*>(
                    &W1[(i * 32 + s) * 128 + j4]);
                a0 = fmaf(xa, w.x, a0); a1 = fmaf(xa, w.y, a1);
                a2 = fmaf(xa, w.z, a2); a3 = fmaf(xa, w.w, a3);
            }
        }
        #pragma unroll
        for (int i = 0; i < 4; i++) {
            const float xc = hc[i];
            #pragma unroll
            for (int s = 0; s < 32; s++) {
                const float xa = __shfl_sync(0xffffffffu, xc, s);
                const float4 w = *reinterpret_cast<const float4*>(
                    &W1[(128 + i * 32 + s) * 128 + j4]);
                a0 = fmaf(xa, w.x, a0); a1 = fmaf(xa, w.y, a1);
                a2 = fmaf(xa, w.z, a2); a3 = fmaf(xa, w.w, a3);
            }
        }
        {
            const float4 w = *reinterpret_cast<const float4*>(&W1[256 * 128 + j4]);
            a0 = fmaf(dist, w.x, a0); a1 = fmaf(dist, w.y, a1);
            a2 = fmaf(dist, w.z, a2); a3 = fmaf(dist, w.w, a3);
        }

        float m[4];
        m[0] = silu_f(a0); m[1] = silu_f(a1); m[2] = silu_f(a2); m[3] = silu_f(a3);

        // ---- layer 2: m @ We2 + be2 ----  (m[k] lives at lane k>>2, slot k&3)
        float c0 = bb2.x, c1 = bb2.y, c2 = bb2.z, c3 = bb2.w;
        #pragma unroll
        for (int q = 0; q < 4; q++) {
            const float xq = m[q];
            #pragma unroll
            for (int s = 0; s < 32; s++) {
                const float xa = __shfl_sync(0xffffffffu, xq, s);
                const float4 w = *reinterpret_cast<const float4*>(
                    &W2[(4 * s + q) * 128 + j4]);
                c0 = fmaf(xa, w.x, c0); c1 = fmaf(xa, w.y, c1);
                c2 = fmaf(xa, w.z, c2); c3 = fmaf(xa, w.w, c3);
            }
        }

        const float r0 = silu_f(c0), r1 = silu_f(c1);
        const float r2 = silu_f(c2), r3 = silu_f(c3);

        float* dst = &g_num[r * 128 + j4];
        atomicAdd(dst + 0, r0);
        atomicAdd(dst + 1, r1);
        atomicAdd(dst + 2, r2);
        atomicAdd(dst + 3, r3);
        if (lane == 0) atomicAdd(&g_deg[r], 1.0f);
    }
}

// ---------------------------------------------------------------------------
// Node kernel: agg = g_num / max(g_deg,1);
//   out = h + silu([h | agg] @ Wn1 + bn1) @ Wn2 + bn2
// ---------------------------------------------------------------------------
__global__ __launch_bounds__(512, 1)
void node_kernel(const float* __restrict__ h,
                 const float* __restrict__ Wn1,
                 const float* __restrict__ bn1,
                 const float* __restrict__ Wn2,
                 const float* __restrict__ bn2,
                 float* __restrict__ out,
                 int N)
{
    extern __shared__ float sm[];
    float* W1 = sm;                       // 256*128
    float* W2 = W1 + 256 * 128;           // 128*128
    float* b1 = W2 + 128 * 128;
    float* b2 = b1 + 128;

    for (int i = threadIdx.x; i < 256 * 128; i += blockDim.x) W1[i] = Wn1[i];
    for (int i = threadIdx.x; i < 128 * 128; i += blockDim.x) W2[i] = Wn2[i];
    if (threadIdx.x < 128)      b1[threadIdx.x] = bn1[threadIdx.x];
    else if (threadIdx.x < 256) b2[threadIdx.x - 128] = bn2[threadIdx.x - 128];
    __syncthreads();

    const int lane = threadIdx.x & 31;
    const int warp = threadIdx.x >> 5;
    const int nwarp = blockDim.x >> 5;
    const int j4 = lane << 2;

    const float4 bb1 = *reinterpret_cast<const float4*>(&b1[j4]);
    const float4 bb2 = *reinterpret_cast<const float4*>(&b2[j4]);

    for (int nd = blockIdx.x * nwarp + warp; nd < N; nd += gridDim.x * nwarp) {
        const float inv = __fdividef(1.0f, fmaxf(g_deg[nd], 1.0f));

        float hn[4], ag[4];
        #pragma unroll
        for (int i = 0; i < 4; i++) {
            hn[i] = h[nd * 128 + i * 32 + lane];
            ag[i] = g_num[nd * 128 + i * 32 + lane] * inv;
        }

        float a0 = bb1.x, a1 = bb1.y, a2 = bb1.z, a3 = bb1.w;
        #pragma unroll
        for (int i = 0; i < 4; i++) {
            const float xh = hn[i];
            #pragma unroll
            for (int s = 0; s < 32; s++) {
                const float xa = __shfl_sync(0xffffffffu, xh, s);
                const float4 w = *reinterpret_cast<const float4*>(
                    &W1[(i * 32 + s) * 128 + j4]);
                a0 = fmaf(xa, w.x, a0); a1 = fmaf(xa, w.y, a1);
                a2 = fmaf(xa, w.z, a2); a3 = fmaf(xa, w.w, a3);
            }
        }
        #pragma unroll
        for (int i = 0; i < 4; i++) {
            const float xg = ag[i];
            #pragma unroll
            for (int s = 0; s < 32; s++) {
                const float xa = __shfl_sync(0xffffffffu, xg, s);
                const float4 w = *reinterpret_cast<const float4*>(
                    &W1[(128 + i * 32 + s) * 128 + j4]);
                a0 = fmaf(xa, w.x, a0); a1 = fmaf(xa, w.y, a1);
                a2 = fmaf(xa, w.z, a2); a3 = fmaf(xa, w.w, a3);
            }
        }

        float m[4];
        m[0] = silu_f(a0); m[1] = silu_f(a1); m[2] = silu_f(a2); m[3] = silu_f(a3);

        float c0 = bb2.x, c1 = bb2.y, c2 = bb2.z, c3 = bb2.w;
        #pragma unroll
        for (int q = 0; q < 4; q++) {
            const float xq = m[q];
            #pragma unroll
            for (int s = 0; s < 32; s++) {
                const float xa = __shfl_sync(0xffffffffu, xq, s);
                const float4 w = *reinterpret_cast<const float4*>(
                    &W2[(4 * s + q) * 128 + j4]);
                c0 = fmaf(xa, w.x, c0); c1 = fmaf(xa, w.y, c1);
                c2 = fmaf(xa, w.z, c2); c3 = fmaf(xa, w.w, c3);
            }
        }

        const float4 hh = *reinterpret_cast<const float4*>(&h[nd * 128 + j4]);
        float4 o;
        o.x = hh.x + c0; o.y = hh.y + c1; o.z = hh.z + c2; o.w = hh.w + c3;
        *reinterpret_cast<float4*>(&out[nd * 128 + j4]) = o;
    }
}

// ---------------------------------------------------------------------------
extern "C" void kernel_launch(void* const* d_in, const int* in_sizes, int n_in,
                              void* d_out, int out_size)
{
    const float* xz  = (const float*)d_in[0];
    const float* h   = (const float*)d_in[1];
    const float* We1 = (const float*)d_in[2];
    const float* be1 = (const float*)d_in[3];
    const float* We2 = (const float*)d_in[4];
    const float* be2 = (const float*)d_in[5];
    const float* Wn1 = (const float*)d_in[6];
    const float* bn1 = (const float*)d_in[7];
    const float* Wn2 = (const float*)d_in[8];
    const float* bn2 = (const float*)d_in[9];
    const int*   ei  = (const int*)d_in[10];

    const int E = in_sizes[10] / 2;
    const int N = in_sizes[1] / 128;
    const int* row = ei;
    const int* col = ei + E;

    int dev = 0, sms = 148;
    cudaGetDevice(&dev);
    cudaDeviceGetAttribute(&sms, cudaDevAttrMultiProcessorCount, dev);

    const size_t smem_edge = (size_t)(257 * 128 + 128 * 128 + 256) * sizeof(float); // 198144
    const size_t smem_node = (size_t)(256 * 128 + 128 * 128 + 256) * sizeof(float); // 197632
    cudaFuncSetAttribute(edge_kernel, cudaFuncAttributeMaxDynamicSharedMemorySize,
                         (int)smem_edge);
    cudaFuncSetAttribute(node_kernel, cudaFuncAttributeMaxDynamicSharedMemorySize,
                         (int)smem_node);

    zero_kernel<<<512, 256>>>(N * HH, N);
    edge_kernel<<<sms, 512, smem_edge>>>(xz, h, We1, be1, We2, be2, row, col, E);
    node_kernel<<<sms, 512, smem_node>>>(h, Wn1, bn1, Wn2, bn2, (float*)d_out, N);
}

// round 2
// speedup vs baseline: 1.8974x; 1.8974x over previous
#include <cuda_runtime.h>
#include <math.h>
#include <stdint.h>

#define NN 50000
#define FF 128
#define HH 128

typedef unsigned long long u64t;

__device__ float g_num[NN * HH];   // per-node message sums
__device__ float g_deg[NN];        // per-node edge counts

// ---------------- f32x2 packed helpers (Blackwell FFMA2 path) ----------------
__device__ __forceinline__ u64t fma2(u64t a, u64t b, u64t c)
{
    u64t d;
    asm("fma.rn.f32x2 %0, %1, %2, %3;" : "=l"(d) : "l"(a), "l"(b), "l"(c));
    return d;
}
__device__ __forceinline__ u64t dup2(float x)
{
    u64t d; unsigned u = __float_as_uint(x);
    asm("mov.b64 %0, {%1, %1};" : "=l"(d) : "r"(u));
    return d;
}
__device__ __forceinline__ float2 unpk(u64t v)
{
    unsigned a, b;
    asm("mov.b64 {%0, %1}, %2;" : "=r"(a), "=r"(b) : "l"(v));
    return make_float2(__uint_as_float(a), __uint_as_float(b));
}
__device__ __forceinline__ float silu_f(float x)
{
    return __fdividef(x, 1.0f + __expf(-x));
}

// ---------------------------------------------------------------------------
__global__ void zero_kernel(int n_num, int n_deg)
{
    int total = n_num + n_deg;
    for (int i = blockIdx.x * blockDim.x + threadIdx.x; i < total;
         i += gridDim.x * blockDim.x) {
        if (i < n_num) g_num[i] = 0.0f;
        else           g_deg[i - n_num] = 0.0f;
    }
}

__global__ void deg_kernel(const int* __restrict__ row, int E)
{
    int e = blockIdx.x * blockDim.x + threadIdx.x;
    if (e < E) atomicAdd(&g_deg[row[e]], 1.0f);
}

// ---------------------------------------------------------------------------
// Edge kernel: T=8 edges per warp, f32x2 accumulators, full weights in SMEM.
// ---------------------------------------------------------------------------
#define T_E 8

__global__ __launch_bounds__(256, 1)
void edge_kernel(const float* __restrict__ xz,
                 const float* __restrict__ h,
                 const float* __restrict__ We1,
                 const float* __restrict__ be1,
                 const float* __restrict__ We2,
                 const float* __restrict__ be2,
                 const int*   __restrict__ row,
                 const int*   __restrict__ col,
                 int E)
{
    extern __shared__ float sm[];
    float* W1 = sm;                       // 257*128
    float* W2 = W1 + 257 * 128;           // 128*128
    float* b1 = W2 + 128 * 128;           // 128
    float* b2 = b1 + 128;                 // 128

    for (int i = threadIdx.x; i < 257 * 128; i += blockDim.x) W1[i] = We1[i];
    for (int i = threadIdx.x; i < 128 * 128; i += blockDim.x) W2[i] = We2[i];
    if (threadIdx.x < 128)      b1[threadIdx.x] = be1[threadIdx.x];
    else if (threadIdx.x < 256) b2[threadIdx.x - 128] = be2[threadIdx.x - 128];
    __syncthreads();

    const int lane  = threadIdx.x & 31;
    const int warp  = threadIdx.x >> 5;
    const int nwarp = blockDim.x >> 5;
    const int j4    = lane << 2;          // outputs j4..j4+3 (= 2 f32x2)

    const ulonglong2 B1 = *reinterpret_cast<const ulonglong2*>(&b1[j4]);
    const ulonglong2 B2 = *reinterpret_cast<const ulonglong2*>(&b2[j4]);

    const int gw     = blockIdx.x * nwarp + warp;
    const int nw_tot = gridDim.x * nwarp;

    for (int e0 = gw * T_E; e0 < E; e0 += nw_tot * T_E) {
        int   r[T_E], c[T_E];
        float dist[T_E];

        #pragma unroll
        for (int t = 0; t < T_E; t++) {
            int e  = e0 + t;
            e      = (e < E) ? e : e0;            // e0 always valid
            int rt = row[e], ct = col[e];
            r[t] = rt; c[t] = ct;
            const float dx = xz[3 * rt + 0] - xz[3 * ct + 0];
            const float dy = xz[3 * rt + 1] - xz[3 * ct + 1];
            const float zr = xz[3 * rt + 2];
            const float zc = xz[3 * ct + 2];
            const float dz = zr - zc;
            const float u  = __fdividef(dx * dx + dy * dy + dz * dz,
                                        2.0f * zr * zc);
            dist[t] = acoshf(1.0f + u);
        }

        u64t a0[T_E], a1[T_E];
        #pragma unroll
        for (int t = 0; t < T_E; t++) { a0[t] = B1.x; a1[t] = B1.y; }

        // ---- phase A: rows 0..127 (source features) ----
        {
            float hr[T_E][4];
            #pragma unroll
            for (int t = 0; t < T_E; t++)
                #pragma unroll
                for (int i = 0; i < 4; i++)
                    hr[t][i] = h[r[t] * 128 + i * 32 + lane];

            #pragma unroll
            for (int i = 0; i < 4; i++) {
                const float* Wrow = &W1[(i * 32) * 128 + j4];
                #pragma unroll 2
                for (int s = 0; s < 32; s++) {
                    const ulonglong2 w =
                        *reinterpret_cast<const ulonglong2*>(Wrow + s * 128);
                    #pragma unroll
                    for (int t = 0; t < T_E; t++) {
                        const u64t xx =
                            dup2(__shfl_sync(0xffffffffu, hr[t][i], s));
                        a0[t] = fma2(xx, w.x, a0[t]);
                        a1[t] = fma2(xx, w.y, a1[t]);
                    }
                }
            }
        }

        // ---- phase B: rows 128..255 (target features) ----
        {
            float hc[T_E][4];
            #pragma unroll
            for (int t = 0; t < T_E; t++)
                #pragma unroll
                for (int i = 0; i < 4; i++)
                    hc[t][i] = h[c[t] * 128 + i * 32 + lane];

            #pragma unroll
            for (int i = 0; i < 4; i++) {
                const float* Wrow = &W1[(128 + i * 32) * 128 + j4];
                #pragma unroll 2
                for (int s = 0; s < 32; s++) {
                    const ulonglong2 w =
                        *reinterpret_cast<const ulonglong2*>(Wrow + s * 128);
                    #pragma unroll
                    for (int t = 0; t < T_E; t++) {
                        const u64t xx =
                            dup2(__shfl_sync(0xffffffffu, hc[t][i], s));
                        a0[t] = fma2(xx, w.x, a0[t]);
                        a1[t] = fma2(xx, w.y, a1[t]);
                    }
                }
            }
        }

        // ---- row 256: distance ----
        {
            const ulonglong2 w =
                *reinterpret_cast<const ulonglong2*>(&W1[256 * 128 + j4]);
            #pragma unroll
            for (int t = 0; t < T_E; t++) {
                const u64t xx = dup2(dist[t]);
                a0[t] = fma2(xx, w.x, a0[t]);
                a1[t] = fma2(xx, w.y, a1[t]);
            }
        }

        // silu -> m
        float m[T_E][4];
        #pragma unroll
        for (int t = 0; t < T_E; t++) {
            const float2 p = unpk(a0[t]);
            const float2 q = unpk(a1[t]);
            m[t][0] = silu_f(p.x); m[t][1] = silu_f(p.y);
            m[t][2] = silu_f(q.x); m[t][3] = silu_f(q.y);
        }

        // ---- layer 2 ----  (input k = 4*s + q lives at lane s, slot q)
        u64t c0[T_E], c1[T_E];
        #pragma unroll
        for (int t = 0; t < T_E; t++) { c0[t] = B2.x; c1[t] = B2.y; }

        #pragma unroll
        for (int q = 0; q < 4; q++) {
            const float* Wrow = &W2[q * 128 + j4];
            #pragma unroll 2
            for (int s = 0; s < 32; s++) {
                const ulonglong2 w =
                    *reinterpret_cast<const ulonglong2*>(Wrow + s * 512);
                #pragma unroll
                for (int t = 0; t < T_E; t++) {
                    const u64t xx = dup2(__shfl_sync(0xffffffffu, m[t][q], s));
                    c0[t] = fma2(xx, w.x, c0[t]);
                    c1[t] = fma2(xx, w.y, c1[t]);
                }
            }
        }

        // silu + vector reduce into g_num
        #pragma unroll
        for (int t = 0; t < T_E; t++) {
            const float2 p = unpk(c0[t]);
            const float2 q = unpk(c1[t]);
            const float r0 = silu_f(p.x), r1 = silu_f(p.y);
            const float r2 = silu_f(q.x), r3 = silu_f(q.y);
            if (e0 + t < E) {
                float* dst = &g_num[r[t] * 128 + j4];
                asm volatile(
                    "red.global.add.v4.f32 [%0], {%1, %2, %3, %4};"
                    :: "l"(dst), "f"(r0), "f"(r1), "f"(r2), "f"(r3)
                    : "memory");
            }
        }
    }
}

// ---------------------------------------------------------------------------
// Node kernel: T=4 nodes per warp, f32x2.
//   out = h + silu([h | g_num/deg] @ Wn1 + bn1) @ Wn2 + bn2
// ---------------------------------------------------------------------------
#define T_N 4

__global__ __launch_bounds__(256, 1)
void node_kernel(const float* __restrict__ h,
                 const float* __restrict__ Wn1,
                 const float* __restrict__ bn1,
                 const float* __restrict__ Wn2,
                 const float* __restrict__ bn2,
                 float* __restrict__ out,
                 int N)
{
    extern __shared__ float sm[];
    float* W1 = sm;                       // 256*128
    float* W2 = W1 + 256 * 128;           // 128*128
    float* b1 = W2 + 128 * 128;
    float* b2 = b1 + 128;

    for (int i = threadIdx.x; i < 256 * 128; i += blockDim.x) W1[i] = Wn1[i];
    for (int i = threadIdx.x; i < 128 * 128; i += blockDim.x) W2[i] = Wn2[i];
    if (threadIdx.x < 128)      b1[threadIdx.x] = bn1[threadIdx.x];
    else if (threadIdx.x < 256) b2[threadIdx.x - 128] = bn2[threadIdx.x - 128];
    __syncthreads();

    const int lane  = threadIdx.x & 31;
    const int warp  = threadIdx.x >> 5;
    const int nwarp = blockDim.x >> 5;
    const int j4    = lane << 2;

    const ulonglong2 B1 = *reinterpret_cast<const ulonglong2*>(&b1[j4]);
    const ulonglong2 B2 = *reinterpret_cast<const ulonglong2*>(&b2[j4]);

    const int gw     = blockIdx.x * nwarp + warp;
    const int nw_tot = gridDim.x * nwarp;

    for (int n0 = gw * T_N; n0 < N; n0 += nw_tot * T_N) {
        int nd[T_N];
        float hn[T_N][4], ag[T_N][4];

        #pragma unroll
        for (int t = 0; t < T_N; t++) {
            int n = n0 + t;
            n = (n < N) ? n : n0;
            nd[t] = n;
            const float inv = __fdividef(1.0f, fmaxf(g_deg[n], 1.0f));
            #pragma unroll
            for (int i = 0; i < 4; i++) {
                hn[t][i] = h[n * 128 + i * 32 + lane];
                ag[t][i] = g_num[n * 128 + i * 32 + lane] * inv;
            }
        }

        u64t a0[T_N], a1[T_N];
        #pragma unroll
        for (int t = 0; t < T_N; t++) { a0[t] = B1.x; a1[t] = B1.y; }

        #pragma unroll
        for (int i = 0; i < 4; i++) {
            const float* Wrow = &W1[(i * 32) * 128 + j4];
            #pragma unroll 2
            for (int s = 0; s < 32; s++) {
                const ulonglong2 w =
                    *reinterpret_cast<const ulonglong2*>(Wrow + s * 128);
                #pragma unroll
                for (int t = 0; t < T_N; t++) {
                    const u64t xx = dup2(__shfl_sync(0xffffffffu, hn[t][i], s));
                    a0[t] = fma2(xx, w.x, a0[t]);
                    a1[t] = fma2(xx, w.y, a1[t]);
                }
            }
        }
        #pragma unroll
        for (int i = 0; i < 4; i++) {
            const float* Wrow = &W1[(128 + i * 32) * 128 + j4];
            #pragma unroll 2
            for (int s = 0; s < 32; s++) {
                const ulonglong2 w =
                    *reinterpret_cast<const ulonglong2*>(Wrow + s * 128);
                #pragma unroll
                for (int t = 0; t < T_N; t++) {
                    const u64t xx = dup2(__shfl_sync(0xffffffffu, ag[t][i], s));
                    a0[t] = fma2(xx, w.x, a0[t]);
                    a1[t] = fma2(xx, w.y, a1[t]);
                }
            }
        }

        float m[T_N][4];
        #pragma unroll
        for (int t = 0; t < T_N; t++) {
            const float2 p = unpk(a0[t]);
            const float2 q = unpk(a1[t]);
            m[t][0] = silu_f(p.x); m[t][1] = silu_f(p.y);
            m[t][2] = silu_f(q.x); m[t][3] = silu_f(q.y);
        }

        u64t c0[T_N], c1[T_N];
        #pragma unroll
        for (int t = 0; t < T_N; t++) { c0[t] = B2.x; c1[t] = B2.y; }

        #pragma unroll
        for (int q = 0; q < 4; q++) {
            const float* Wrow = &W2[q * 128 + j4];
            #pragma unroll 2
            for (int s = 0; s < 32; s++) {
                const ulonglong2 w =
                    *reinterpret_cast<const ulonglong2*>(Wrow + s * 512);
                #pragma unroll
                for (int t = 0; t < T_N; t++) {
                    const u64t xx = dup2(__shfl_sync(0xffffffffu, m[t][q], s));
                    c0[t] = fma2(xx, w.x, c0[t]);
                    c1[t] = fma2(xx, w.y, c1[t]);
                }
            }
        }

        #pragma unroll
        for (int t = 0; t < T_N; t++) {
            if (n0 + t < N) {
                const float2 p = unpk(c0[t]);
                const float2 q = unpk(c1[t]);
                const float4 hh = *reinterpret_cast<const float4*>(
                    &h[nd[t] * 128 + j4]);
                float4 o;
                o.x = hh.x + p.x; o.y = hh.y + p.y;
                o.z = hh.z + q.x; o.w = hh.w + q.y;
                *reinterpret_cast<float4*>(&out[nd[t] * 128 + j4]) = o;
            }
        }
    }
}

// ---------------------------------------------------------------------------
extern "C" void kernel_launch(void* const* d_in, const int* in_sizes, int n_in,
                              void* d_out, int out_size)
{
    const float* xz  = (const float*)d_in[0];
    const float* h   = (const float*)d_in[1];
    const float* We1 = (const float*)d_in[2];
    const float* be1 = (const float*)d_in[3];
    const float* We2 = (const float*)d_in[4];
    const float* be2 = (const float*)d_in[5];
    const float* Wn1 = (const float*)d_in[6];
    const float* bn1 = (const float*)d_in[7];
    const float* Wn2 = (const float*)d_in[8];
    const float* bn2 = (const float*)d_in[9];
    const int*   ei  = (const int*)d_in[10];

    const int E = in_sizes[10] / 2;
    const int N = in_sizes[1] / 128;
    const int* row = ei;
    const int* col = ei + E;

    int dev = 0, sms = 148;
    cudaGetDevice(&dev);
    cudaDeviceGetAttribute(&sms, cudaDevAttrMultiProcessorCount, dev);

    const size_t smem_edge = (size_t)(257 * 128 + 128 * 128 + 256) * sizeof(float);
    const size_t smem_node = (size_t)(256 * 128 + 128 * 128 + 256) * sizeof(float);
    cudaFuncSetAttribute(edge_kernel, cudaFuncAttributeMaxDynamicSharedMemorySize,
                         (int)smem_edge);
    cudaFuncSetAttribute(node_kernel, cudaFuncAttributeMaxDynamicSharedMemorySize,
                         (int)smem_node);

    zero_kernel<<<512, 256>>>(N * HH, N);
    deg_kernel<<<(E + 255) / 256, 256>>>(row, E);
    edge_kernel<<<sms, 256, smem_edge>>>(xz, h, We1, be1, We2, be2, row, col, E);
    node_kernel<<<sms, 256, smem_node>>>(h, Wn1, bn1, Wn2, bn2, (float*)d_out, N);
}